// round 14
// baseline (speedup 1.0000x reference)
#include <cuda_runtime.h>
#include <math.h>

#define NC 1000
#define NA 64
#define FPSCALE 4398046511104.0f   // 2^42, exact in float

// Scratch + cross-kernel accumulators. __device__ globals (no allocation).
// g_sum / g_key are ORDER-INDEPENDENT accumulators (integer add / max), so
// they are bit-deterministic; solve_kernel resets them for graph replays.
__device__ float g_pp[1024];
__device__ float g_som[128];
__device__ int   g_nm1;
__device__ unsigned long long g_sum = 0;   // sum(exp(pp)) in 2^-42 fixed point
__device__ unsigned long long g_key = 0;   // argmax(p0): (bits(p0)<<32)|(1023-row)

// Kernel 1: blocks 0..124: pp rows + per-block partial {sum exp(pp), argmax p0}.
//           block 125:     omega table (exact float recurrence) + underflow idx.
__global__ void pp_kernel(const float* __restrict__ W, const float* __restrict__ P,
                          const float* __restrict__ p0,
                          const float* __restrict__ omega) {
    const unsigned FULL = 0xffffffffu;
    int tid  = threadIdx.x;
    int lane = tid & 31;
    int wid  = tid >> 5;

    if (blockIdx.x == 125) {
        __shared__ unsigned sb[4];
        if (tid < 128) {
            float w0 = omega[0];
            w0 = fminf(fmaxf(w0, 0.0f), 1.0f);
            float cur = w0;
            #pragma unroll
            for (int k = 0; k < 127; ++k)
                if (k < tid) cur -= 0.01f;          // exact float recurrence
            g_som[tid] = cur;
            unsigned b = __ballot_sync(FULL, (cur - 0.01f) < 0.001f);
            if (lane == 0) sb[wid] = b;
        }
        __syncthreads();
        if (tid == 0) {
            int nm1 = 127;                          // forced underflow index
            #pragma unroll
            for (int w = 0; w < 4; ++w)
                if (sb[w]) { nm1 = w * 32 + __ffs(sb[w]) - 1; break; }
            g_nm1 = nm1;
        }
        return;
    }

    __shared__ float se[8];
    __shared__ unsigned long long sk[8];

    int row = (blockIdx.x * blockDim.x + tid) >> 5;   // rows 0..999 (exact)
    const float2* w2 = reinterpret_cast<const float2*>(W + row * NA);
    const float2* p2 = reinterpret_cast<const float2*>(P + row * NA);
    float2 w = w2[lane];
    float2 p = p2[lane];
    float s = w.x * p.x + w.y * p.y;
    #pragma unroll
    for (int off = 16; off; off >>= 1)
        s += __shfl_down_sync(FULL, s, off);
    if (lane == 0) {
        g_pp[row] = s;
        se[wid] = __expf(s);
        float pv = p0[row];
        sk[wid] = ((unsigned long long)__float_as_uint(pv) << 32)
                | (unsigned long long)(1023 - row);   // larger key = smaller row
    }
    __syncthreads();
    if (tid == 0) {
        unsigned long long tot = 0, mk = 0;
        #pragma unroll
        for (int w = 0; w < 8; ++w) {
            tot += (unsigned long long)llrintf(se[w] * FPSCALE);  // exact int sum
            mk = (sk[w] > mk) ? sk[w] : mk;
        }
        atomicAdd(&g_sum, tot);     // integer: order-independent, deterministic
        atomicMax(&g_key, mk);      // max: order-independent, deterministic
    }
}

// Kernel 2: minimal 1024-thread solver — TWO barriers, no Phase-A reductions.
//   Scalars (sumexp, c, p0c) come pre-reduced from pp_kernel's atomics.
//   Local per-class exact stop index t_j (analytic crossover + 5-point exact
//   float check vs the omega table, read straight from L2).  One max-reduce.
__global__ __launch_bounds__(1024) void solve_kernel(const float* __restrict__ p0,
                                                     float* __restrict__ out) {
    __shared__ int b_t[32];
    __shared__ int s_istar;

    const unsigned FULL = 0xffffffffu;
    int tid  = threadIdx.x;
    int lane = tid & 31;
    int wid  = tid >> 5;
    bool live = (tid < NC);

    // ---- Uniform scalar loads (L2 broadcast) + per-class loads ----
    unsigned long long S = g_sum;
    unsigned long long K = g_key;
    int   nm1 = g_nm1;
    float w0  = g_som[0];
    float p0v = live ? p0[tid]   : -INFINITY;
    float ppv = live ? g_pp[tid] : 0.0f;

    float sumexp = (float)S * (1.0f / FPSCALE);
    float inv    = 1.0f / sumexp;
    int   c      = 1023 - (int)(K & 1023u);
    float p0c    = __uint_as_float((unsigned)(K >> 32));
    float ppc    = g_pp[c];                 // dependent load, L2
    float qv     = __expf(ppv) * inv;
    float qc     = __expf(ppc) * inv;       // bitwise == owner's qv

    // ---- Local exact stop index t_j (no sync) ----
    // Violation (j beats c): j<c needs vj >= vc ; j>c needs vj > vc.
    // d(w) = (1-w)A + wB, A = p0c-p0j > 0.  No crossover => t=0.  Else real
    // crossover theta = A/(A-B); the float transition lies within +-1 step of
    // it (margin 0.01*(A-B) >> float noise), so a 5-point exact float check
    // starting 2 steps early resolves t exactly.  Capped at nm1 (underflow).
    int t = 0;
    if (live && tid != c) {
        float A = p0c - p0v;
        float B = qc  - qv;
        bool cross = (tid < c) ? (B <= 0.0f) : (B < 0.0f);
        if (cross) {
            float theta = A / (A - B);
            int ie = (int)ceilf((w0 - theta) * 100.0f);
            int s0 = ie - 2;
            if (s0 < 0) s0 = 0;
            if (s0 > nm1) s0 = nm1;
            t = nm1;                        // default: violating to the end
            bool found = false;
            #pragma unroll
            for (int s = 0; s < 5; ++s) {
                int i = s0 + s;
                if (i > nm1) i = nm1;
                float cw   = __ldcg(&g_som[i]);   // L2 (written by pp_kernel)
                float onem = 1.0f - cw;
                float vc = onem * p0c + cw * qc;
                float vj = onem * p0v + cw * qv;
                bool viol = (tid < c) ? (vj >= vc) : (vj > vc);
                if (!found && !viol) { t = i; found = true; }
            }
        }
    }

    // ---- istar = max_j t_j : REDUX per warp, stage 2 on warp 0 ----
    {
        int m = __reduce_max_sync(FULL, t);
        if (lane == 0) b_t[wid] = m;
    }
    __syncthreads();                        // barrier 1
    if (wid == 0) {
        int m = __reduce_max_sync(FULL, b_t[lane]);
        if (lane == 0) s_istar = m;
    }
    __syncthreads();                        // barrier 2

    // ---- Output: p = (1-omega*) * p0 + omega* * q, shape (1, NC) ----
    float om = __ldcg(&g_som[s_istar]);     // uniform broadcast load
    if (live)
        out[tid] = (1.0f - om) * p0v + om * qv;

    // ---- Reset accumulators for the next graph replay (all reads done) ----
    if (tid == 0) { g_sum = 0ULL; g_key = 0ULL; }
}

extern "C" void kernel_launch(void* const* d_in, const int* in_sizes, int n_in,
                              void* d_out, int out_size) {
    const float* p0 = (const float*)d_in[0];
    const float* P  = (const float*)d_in[1];
    const float* W  = (const float*)d_in[2];
    const float* om = (const float*)d_in[3];
    float* out = (float*)d_out;

    pp_kernel<<<126, 256>>>(W, P, p0, om);
    solve_kernel<<<1, 1024>>>(p0, out);
}

// round 15
// speedup vs baseline: 1.0428x; 1.0428x over previous
#include <cuda_runtime.h>
#include <math.h>

#define NC 1000
#define NA 64
#define FPSCALE 4398046511104.0f   // 2^42, exact in float

// Scratch + cross-kernel accumulators. __device__ globals (no allocation).
// g_sum / g_key are ORDER-INDEPENDENT accumulators (integer add / max) =>
// bit-deterministic under any atomic ordering; solve_kernel resets them.
__device__ float g_pp[1024];
__device__ float g_som[128];
__device__ int   g_nm1;
__device__ unsigned long long g_sum = 0;   // sum(exp(pp)) in 2^-42 fixed point
__device__ unsigned long long g_key = 0;   // argmax(p0): (bits(p0)<<32)|(1023-row)

// Kernel 1: blocks 0..124: pp rows; per-WARP fire-and-forget REDs (no block
//           combine, no __syncthreads tail).  block 125: omega table.
__global__ void pp_kernel(const float* __restrict__ W, const float* __restrict__ P,
                          const float* __restrict__ p0,
                          const float* __restrict__ omega) {
    const unsigned FULL = 0xffffffffu;
    int tid  = threadIdx.x;
    int lane = tid & 31;
    int wid  = tid >> 5;

    if (blockIdx.x == 125) {
        __shared__ unsigned sb[4];
        if (tid < 128) {
            float w0 = omega[0];
            w0 = fminf(fmaxf(w0, 0.0f), 1.0f);
            float cur = w0;
            #pragma unroll
            for (int k = 0; k < 127; ++k)
                if (k < tid) cur -= 0.01f;          // exact float recurrence
            g_som[tid] = cur;
            unsigned b = __ballot_sync(FULL, (cur - 0.01f) < 0.001f);
            if (lane == 0) sb[wid] = b;
        }
        __syncthreads();
        if (tid == 0) {
            int nm1 = 127;                          // forced underflow index
            #pragma unroll
            for (int w = 0; w < 4; ++w)
                if (sb[w]) { nm1 = w * 32 + __ffs(sb[w]) - 1; break; }
            g_nm1 = nm1;
        }
        return;
    }

    int row = (blockIdx.x * blockDim.x + tid) >> 5;   // rows 0..999 exactly
    const float2* w2 = reinterpret_cast<const float2*>(W + row * NA);
    const float2* p2 = reinterpret_cast<const float2*>(P + row * NA);
    float2 w = w2[lane];
    float2 p = p2[lane];
    float s = w.x * p.x + w.y * p.y;
    #pragma unroll
    for (int off = 16; off; off >>= 1)
        s += __shfl_down_sync(FULL, s, off);
    if (lane == 0) {
        g_pp[row] = s;
        // Fire-and-forget REDs (results discarded => REDG, no return wait).
        // Integer add / max: order-independent => deterministic.
        atomicAdd(&g_sum, (unsigned long long)llrintf(__expf(s) * FPSCALE));
        unsigned long long key =
            ((unsigned long long)__float_as_uint(p0[row]) << 32)
            | (unsigned long long)(1023 - row);       // larger key = smaller row
        atomicMax(&g_key, key);
    }
}

// Kernel 2: minimal 1024-thread solver.  All block reductions pre-done by
// pp_kernel's atomics.  som staged to SMEM; pp[c] broadcast by thread c via
// SMEM (no dependent L2 load).  3 barriers total.
__global__ __launch_bounds__(1024) void solve_kernel(const float* __restrict__ p0,
                                                     float* __restrict__ out) {
    __shared__ float som[128];
    __shared__ float s_ppc;
    __shared__ int   b_t[32];
    __shared__ int   s_istar;

    const unsigned FULL = 0xffffffffu;
    int tid  = threadIdx.x;
    int lane = tid & 31;
    int wid  = tid >> 5;
    bool live = (tid < NC);

    // ---- Independent early loads (all overlap) ----
    if (tid < 128) som[tid] = g_som[tid];           // stage omega table to SMEM
    unsigned long long S = g_sum;
    unsigned long long K = g_key;
    int   nm1 = g_nm1;
    float p0v = live ? p0[tid]   : -INFINITY;
    float ppv = live ? g_pp[tid] : 0.0f;

    int   c   = 1023 - (int)(K & 1023u);
    float p0c = __uint_as_float((unsigned)(K >> 32));
    if (tid == c) s_ppc = ppv;                      // broadcast pp[c] via SMEM
    __syncthreads();                                // barrier A: som + s_ppc

    float sumexp = (float)S * (1.0f / FPSCALE);
    float inv    = 1.0f / sumexp;
    float qv     = __expf(ppv) * inv;
    float qc     = __expf(s_ppc) * inv;             // bitwise == owner's qv
    float w0     = som[0];

    // ---- Local exact stop index t_j (no sync) ----
    // Violation (j beats c): j<c needs vj >= vc ; j>c needs vj > vc.
    // d(w) = (1-w)A + wB, A = p0c-p0j > 0.  No crossover => t=0.  Else real
    // crossover theta = A/(A-B); the float transition lies within +-1 step
    // (margin 0.01*(A-B) >> float noise): a 5-point exact float check
    // starting 2 steps early resolves t exactly.  Capped at nm1 (underflow).
    int t = 0;
    if (live && tid != c) {
        float A = p0c - p0v;
        float B = qc  - qv;
        bool cross = (tid < c) ? (B <= 0.0f) : (B < 0.0f);
        if (cross) {
            float theta = A / (A - B);
            int ie = (int)ceilf((w0 - theta) * 100.0f);
            int s0 = ie - 2;
            if (s0 < 0) s0 = 0;
            if (s0 > nm1) s0 = nm1;
            t = nm1;                        // default: violating to the end
            bool found = false;
            #pragma unroll
            for (int s = 0; s < 5; ++s) {
                int i = s0 + s;
                if (i > nm1) i = nm1;
                float cw   = som[i];        // SMEM, 29 cyc
                float onem = 1.0f - cw;
                float vc = onem * p0c + cw * qc;
                float vj = onem * p0v + cw * qv;
                bool viol = (tid < c) ? (vj >= vc) : (vj > vc);
                if (!found && !viol) { t = i; found = true; }
            }
        }
    }

    // ---- istar = max_j t_j : REDUX per warp, stage 2 on warp 0 ----
    {
        int m = __reduce_max_sync(FULL, t);
        if (lane == 0) b_t[wid] = m;
    }
    __syncthreads();                        // barrier B
    if (wid == 0) {
        int m = __reduce_max_sync(FULL, b_t[lane]);
        if (lane == 0) s_istar = m;
    }
    __syncthreads();                        // barrier C

    // ---- Output: p = (1-omega*) * p0 + omega* * q, shape (1, NC) ----
    float om = som[s_istar];                // SMEM broadcast
    if (live)
        out[tid] = (1.0f - om) * p0v + om * qv;

    // ---- Reset accumulators for the next graph replay (all reads done) ----
    if (tid == 0) { g_sum = 0ULL; g_key = 0ULL; }
}

extern "C" void kernel_launch(void* const* d_in, const int* in_sizes, int n_in,
                              void* d_out, int out_size) {
    const float* p0 = (const float*)d_in[0];
    const float* P  = (const float*)d_in[1];
    const float* W  = (const float*)d_in[2];
    const float* om = (const float*)d_in[3];
    float* out = (float*)d_out;

    pp_kernel<<<126, 256>>>(W, P, p0, om);
    solve_kernel<<<1, 1024>>>(p0, out);
}